// round 5
// baseline (speedup 1.0000x reference)
#include <cuda_runtime.h>
#include <cstdint>
#include <cstddef>

// ---------------- problem constants ----------------
#define T_LEN   16384
#define NTOT    131072        // 8 * 16384
#define RESC    120
#define SKIPC   240
#define NQ      256
#define NBLK    16

// ---------------- device scratch ----------------
__device__ __align__(16) float g_X   [RESC * NTOT];          // residual
__device__ __align__(16) float g_Zall[(size_t)NBLK * 128 * NTOT]; // all gated acts (pad 128 rows/layer)
__device__ __align__(16) float g_SK  [256 * NTOT];           // relu(skip_sum), padded to 256 rows
__device__ __align__(16) float g_H   [256 * NTOT];           // hidden after head1

// packed weights [K][Mpad], zero-padded
__device__ __align__(16) float g_Wfg[NBLK * 240 * 256];
__device__ __align__(16) float g_Bfg[NBLK * 256];
__device__ __align__(16) float g_Wrs[NBLK * 128 * 128];
__device__ __align__(16) float g_Brs[NBLK * 128];
__device__ __align__(16) float g_Wsk[2048 * 256];            // K = 16 layers x 128 (pad), M = 256
__device__ __align__(16) float g_Bsk[256];
__device__ __align__(16) float g_W1p[256 * 256];             // K padded 240->256
__device__ __align__(16) float g_W2p[256 * 256];

// ---------------- f32x2 helpers ----------------
#define FMA2(acc, a, b) asm("fma.rn.f32x2 %0, %1, %2, %0;" : "+l"(acc) : "l"(a), "l"(b))
#define UNPACK2(lo, hi, v) do { unsigned int _u0, _u1; \
    asm("mov.b64 {%0, %1}, %2;" : "=r"(_u0), "=r"(_u1) : "l"(v)); \
    lo = __uint_as_float(_u0); hi = __uint_as_float(_u1); } while (0)

__device__ __forceinline__ float safe_tanh(float x) {
    float ax = fabsf(x);
    float e  = __expf(-2.0f * ax);
    float t  = (1.0f - e) / (1.0f + e);
    return copysignf(t, x);
}
__device__ __forceinline__ float sigmoidf_(float x) {
    return 1.0f / (1.0f + __expf(-x));
}

// ---------------- packing kernels ----------------
__global__ void pack_fg_kernel(const float* __restrict__ Wf, const float* __restrict__ bf,
                               const float* __restrict__ Wg, const float* __restrict__ bg) {
    int idx = blockIdx.x * blockDim.x + threadIdx.x;
    const int total = NBLK * 240 * 256;
    if (idx < total) {
        int m = idx & 255;
        int k = (idx >> 8) % 240;
        int i = idx / (240 * 256);
        int c = m >> 1, isg = m & 1;
        float v = 0.0f;
        if (c < RESC) {
            int kc = k % RESC, tap = k / RESC;   // tap0 -> x[t-d], tap1 -> x[t]
            const float* src = isg ? Wg : Wf;
            v = src[(((size_t)i * RESC + c) * RESC + kc) * 2 + tap];
        }
        g_Wfg[idx] = v;
    }
    if (idx < NBLK * 256) {
        int m = idx & 255; int i = idx >> 8;
        int c = m >> 1, isg = m & 1;
        g_Bfg[idx] = (c < RESC) ? (isg ? bg[i * RESC + c] : bf[i * RESC + c]) : 0.0f;
    }
}

__global__ void pack_rs_kernel(const float* __restrict__ Wres, const float* __restrict__ bres) {
    int idx = blockIdx.x * blockDim.x + threadIdx.x;
    const int total = NBLK * 128 * 128;
    if (idx < total) {
        int m = idx & 127;
        int k = (idx >> 7) & 127;
        int i = idx >> 14;
        float v = 0.0f;
        if (k < RESC && m < RESC) v = Wres[((size_t)i * RESC + m) * RESC + k];
        g_Wrs[idx] = v;
    }
    if (idx < NBLK * 128) {
        int m = idx & 127; int i = idx >> 7;
        g_Brs[idx] = (m < RESC) ? bres[i * RESC + m] : 0.0f;
    }
}

__global__ void pack_sk_kernel(const float* __restrict__ Wskip, const float* __restrict__ bskip) {
    int idx = blockIdx.x * blockDim.x + threadIdx.x;
    const int total = 2048 * 256;
    if (idx < total) {
        int m = idx & 255;
        int k = idx >> 8;
        int layer = k >> 7, c = k & 127;
        float v = 0.0f;
        if (c < RESC && m < SKIPC)
            v = Wskip[((size_t)layer * SKIPC + m) * RESC + c];
        g_Wsk[idx] = v;
    }
    if (idx < 256) {
        float s = 0.0f;
        if (idx < SKIPC)
            for (int l = 0; l < NBLK; l++) s += bskip[l * SKIPC + idx];
        g_Bsk[idx] = s;
    }
}

__global__ void pack_heads_kernel(const float* __restrict__ W1, const float* __restrict__ W2) {
    int idx = blockIdx.x * blockDim.x + threadIdx.x;
    if (idx < 256 * 256) {
        int m = idx & 255; int k = idx >> 8;
        g_W1p[idx] = (k < 240) ? W1[(size_t)m * 240 + k] : 0.0f;
        g_W2p[idx] = W2[(size_t)m * 256 + k];
    }
}

__global__ void init_kernel(const float* __restrict__ wave,
                            const float* __restrict__ W_in,
                            const float* __restrict__ b_in) {
    int idx = blockIdx.x * blockDim.x + threadIdx.x;
    int r = idx >> 17;
    int n = idx & (NTOT - 1);
    g_X[(size_t)r * NTOT + n] = W_in[r] * wave[n] + b_in[r];
}

// ---------------- pipelined fused GEMM: CTA 128x128, thread 8x8 ----------------
// IN_MODE : 0 = dilated concat from g_X, 1 = plain
// OUT_MODE: 0 = FG (tanh*sig -> z layer), 1 = res (+= g_X), 2 = skip relu -> g_SK,
//           3 = head1 relu -> g_H, 4 = logits -> dout
template<int K, int IN_MODE, int OUT_MODE, int MP, int DALIGN>
__global__ void __launch_bounds__(256, 2) gemm_kernel(int blk, int d,
                                                      const float* __restrict__ bias_ext,
                                                      float* __restrict__ dout) {
    __shared__ float Ws[16][256];   // duplicated: Ws[k][2m] = Ws[k][2m+1] = W[k][m]
    __shared__ float Xs[16][128];

    const int tid = threadIdx.x;
    const int w = tid >> 5, l = tid & 31;
    const int my = (w >> 1) * 4 + (l >> 3);   // 0..15, row group (8 rows)
    const int nx = (w & 1) * 8 + (l & 7);     // 0..15, col group (8 cols)
    const int n0 = blockIdx.x * 128;
    const int mbase = blockIdx.y * 128;
    const bool first_tile = ((n0 & (T_LEN - 1)) == 0);

    const float* W; const float* bias; const float* Xin; float* Out;
    if (OUT_MODE == 0)      { W = g_Wfg + (size_t)blk * 240 * 256; bias = g_Bfg + blk * 256;
                              Xin = g_X; Out = g_Zall + (size_t)blk * 128 * NTOT; }
    else if (OUT_MODE == 1) { W = g_Wrs + (size_t)blk * 128 * 128; bias = g_Brs + blk * 128;
                              Xin = g_Zall + (size_t)blk * 128 * NTOT; Out = g_X; }
    else if (OUT_MODE == 2) { W = g_Wsk; bias = g_Bsk; Xin = g_Zall; Out = g_SK; }
    else if (OUT_MODE == 3) { W = g_W1p; bias = bias_ext; Xin = g_SK; Out = g_H; }
    else                    { W = g_W2p; bias = bias_ext; Xin = g_H; Out = dout; }

    unsigned long long acc[8][4];
#pragma unroll
    for (int r = 0; r < 8; r++)
#pragma unroll
        for (int c = 0; c < 4; c++) acc[r][c] = 0ull;

    float4 wst[2], xst[2];

    // ---- register-stage loader for chunk starting at kc ----
#define LOAD_CHUNK(kc) do {                                                     \
        _Pragma("unroll")                                                       \
        for (int i = 0; i < 2; i++) {                                           \
            int e4 = tid + i * 256;                                             \
            int kr = e4 >> 5, m4 = e4 & 31;                                     \
            wst[i] = *(const float4*)(W + (size_t)((kc) + kr) * MP + mbase + m4 * 4); \
        }                                                                       \
        _Pragma("unroll")                                                       \
        for (int i = 0; i < 2; i++) {                                           \
            int e4 = tid + i * 256;                                             \
            int kr = e4 >> 5, nl4 = e4 & 31;                                    \
            int kk = (kc) + kr;                                                 \
            int n = n0 + nl4 * 4;                                               \
            float4 v;                                                           \
            if (IN_MODE == 0) {                                                 \
                if (kk < RESC) {                                                \
                    const float* src = Xin + (size_t)kk * NTOT + n - d;         \
                    if (first_tile) {                                           \
                        int t = nl4 * 4;                                        \
                        v.x = (t + 0 >= d) ? src[0] : 0.0f;                     \
                        v.y = (t + 1 >= d) ? src[1] : 0.0f;                     \
                        v.z = (t + 2 >= d) ? src[2] : 0.0f;                     \
                        v.w = (t + 3 >= d) ? src[3] : 0.0f;                     \
                    } else if (DALIGN == 4) {                                   \
                        v = *(const float4*)src;                                \
                    } else if (DALIGN == 2) {                                   \
                        float2 a = *(const float2*)src;                         \
                        float2 b = *(const float2*)(src + 2);                   \
                        v.x = a.x; v.y = a.y; v.z = b.x; v.w = b.y;             \
                    } else {                                                    \
                        v.x = src[0]; v.y = src[1]; v.z = src[2]; v.w = src[3]; \
                    }                                                           \
                } else {                                                        \
                    v = *(const float4*)(Xin + (size_t)(kk - RESC) * NTOT + n); \
                }                                                               \
            } else {                                                            \
                v = *(const float4*)(Xin + (size_t)kk * NTOT + n);              \
            }                                                                   \
            xst[i] = v;                                                         \
        }                                                                       \
    } while (0)

    LOAD_CHUNK(0);

    const int NC = K / 16;
#pragma unroll 1
    for (int c = 0; c < NC; c++) {
        __syncthreads();   // previous compute done reading SMEM
        // ---- STS staged regs (W duplicated) ----
#pragma unroll
        for (int i = 0; i < 2; i++) {
            int e4 = tid + i * 256;
            int kr = e4 >> 5, m4 = e4 & 31;
            float4 v = wst[i];
            float4 a = make_float4(v.x, v.x, v.y, v.y);
            float4 b = make_float4(v.z, v.z, v.w, v.w);
            *(float4*)&Ws[kr][m4 * 8] = a;
            *(float4*)&Ws[kr][m4 * 8 + 4] = b;
        }
#pragma unroll
        for (int i = 0; i < 2; i++) {
            int e4 = tid + i * 256;
            int kr = e4 >> 5, nl4 = e4 & 31;
            *(float4*)&Xs[kr][nl4 * 4] = xst[i];
        }
        __syncthreads();
        if (c + 1 < NC) LOAD_CHUNK((c + 1) * 16);

        // ---- compute 16 k-steps ----
#pragma unroll
        for (int k = 0; k < 16; k++) {
            ulonglong2 w0 = *(const ulonglong2*)&Ws[k][my * 16];
            ulonglong2 w1 = *(const ulonglong2*)&Ws[k][my * 16 + 4];
            ulonglong2 w2 = *(const ulonglong2*)&Ws[k][my * 16 + 8];
            ulonglong2 w3 = *(const ulonglong2*)&Ws[k][my * 16 + 12];
            ulonglong2 xa = *(const ulonglong2*)&Xs[k][nx * 8];
            ulonglong2 xb = *(const ulonglong2*)&Xs[k][nx * 8 + 4];
            FMA2(acc[0][0], w0.x, xa.x); FMA2(acc[0][1], w0.x, xa.y);
            FMA2(acc[0][2], w0.x, xb.x); FMA2(acc[0][3], w0.x, xb.y);
            FMA2(acc[1][0], w0.y, xa.x); FMA2(acc[1][1], w0.y, xa.y);
            FMA2(acc[1][2], w0.y, xb.x); FMA2(acc[1][3], w0.y, xb.y);
            FMA2(acc[2][0], w1.x, xa.x); FMA2(acc[2][1], w1.x, xa.y);
            FMA2(acc[2][2], w1.x, xb.x); FMA2(acc[2][3], w1.x, xb.y);
            FMA2(acc[3][0], w1.y, xa.x); FMA2(acc[3][1], w1.y, xa.y);
            FMA2(acc[3][2], w1.y, xb.x); FMA2(acc[3][3], w1.y, xb.y);
            FMA2(acc[4][0], w2.x, xa.x); FMA2(acc[4][1], w2.x, xa.y);
            FMA2(acc[4][2], w2.x, xb.x); FMA2(acc[4][3], w2.x, xb.y);
            FMA2(acc[5][0], w2.y, xa.x); FMA2(acc[5][1], w2.y, xa.y);
            FMA2(acc[5][2], w2.y, xb.x); FMA2(acc[5][3], w2.y, xb.y);
            FMA2(acc[6][0], w3.x, xa.x); FMA2(acc[6][1], w3.x, xa.y);
            FMA2(acc[6][2], w3.x, xb.x); FMA2(acc[6][3], w3.x, xb.y);
            FMA2(acc[7][0], w3.y, xa.x); FMA2(acc[7][1], w3.y, xa.y);
            FMA2(acc[7][2], w3.y, xb.x); FMA2(acc[7][3], w3.y, xb.y);
        }
    }
#undef LOAD_CHUNK

    const int ncolb = n0 + nx * 8;

    if (OUT_MODE == 0) {
        // rows are (f,g) interleaved pairs -> z = tanh(f)*sigmoid(g)
#pragma unroll
        for (int p = 0; p < 4; p++) {
            int m = mbase + my * 8 + 2 * p;
            int c = m >> 1;
            if (c < RESC) {
                float bfv = bias[m], bgv = bias[m + 1];
#pragma unroll
                for (int cp = 0; cp < 4; cp++) {
                    float flo, fhi, glo, ghi;
                    UNPACK2(flo, fhi, acc[2 * p][cp]);
                    UNPACK2(glo, ghi, acc[2 * p + 1][cp]);
                    float2 z;
                    z.x = safe_tanh(flo + bfv) * sigmoidf_(glo + bgv);
                    z.y = safe_tanh(fhi + bfv) * sigmoidf_(ghi + bgv);
                    *(float2*)&Out[(size_t)c * NTOT + ncolb + cp * 2] = z;
                }
            }
        }
    } else if (OUT_MODE == 1) {
#pragma unroll
        for (int r = 0; r < 8; r++) {
            int m = my * 8 + r;
            if (m < RESC) {
                float bv = bias[m];
                float* tgt = &Out[(size_t)m * NTOT + ncolb];
#pragma unroll
                for (int cp = 0; cp < 4; cp++) {
                    float lo, hi;
                    UNPACK2(lo, hi, acc[r][cp]);
                    float2 cur = *(float2*)(tgt + cp * 2);
                    cur.x += lo + bv; cur.y += hi + bv;
                    *(float2*)(tgt + cp * 2) = cur;
                }
            }
        }
    } else if (OUT_MODE == 2 || OUT_MODE == 3) {
#pragma unroll
        for (int r = 0; r < 8; r++) {
            int m = mbase + my * 8 + r;
            float bv = bias[m];
#pragma unroll
            for (int cp = 0; cp < 4; cp++) {
                float lo, hi;
                UNPACK2(lo, hi, acc[r][cp]);
                float2 o;
                o.x = fmaxf(lo + bv, 0.0f);
                o.y = fmaxf(hi + bv, 0.0f);
                *(float2*)&Out[(size_t)m * NTOT + ncolb + cp * 2] = o;
            }
        }
    } else {
        int b = n0 >> 14;
        int t0 = ncolb & (T_LEN - 1);
#pragma unroll
        for (int r = 0; r < 8; r++) {
            int m = mbase + my * 8 + r;
            float bv = bias[m];
#pragma unroll
            for (int cp = 0; cp < 4; cp++) {
                float lo, hi;
                UNPACK2(lo, hi, acc[r][cp]);
                float2 o; o.x = lo + bv; o.y = hi + bv;
                *(float2*)&Out[((size_t)b * NQ + m) * T_LEN + t0 + cp * 2] = o;
            }
        }
    }
}

// ---------------- launch ----------------
extern "C" void kernel_launch(void* const* d_in, const int* in_sizes, int n_in,
                              void* d_out, int out_size) {
    const float* wave  = (const float*)d_in[0];
    const float* W_in  = (const float*)d_in[1];
    const float* b_in  = (const float*)d_in[2];
    const float* Wf    = (const float*)d_in[3];
    const float* bf    = (const float*)d_in[4];
    const float* Wg    = (const float*)d_in[5];
    const float* bg    = (const float*)d_in[6];
    const float* Wres  = (const float*)d_in[7];
    const float* bres  = (const float*)d_in[8];
    const float* Wskip = (const float*)d_in[9];
    const float* bskip = (const float*)d_in[10];
    const float* W1    = (const float*)d_in[11];
    const float* b1    = (const float*)d_in[12];
    const float* W2    = (const float*)d_in[13];
    const float* b2    = (const float*)d_in[14];
    float* out = (float*)d_out;

    pack_fg_kernel<<<(NBLK * 240 * 256 + 255) / 256, 256>>>(Wf, bf, Wg, bg);
    pack_rs_kernel<<<(NBLK * 128 * 128 + 255) / 256, 256>>>(Wres, bres);
    pack_sk_kernel<<<(2048 * 256 + 255) / 256, 256>>>(Wskip, bskip);
    pack_heads_kernel<<<(256 * 256 + 255) / 256, 256>>>(W1, W2);
    init_kernel<<<(RESC * NTOT) / 256, 256>>>(wave, W_in, b_in);

    static const int dil[NBLK] = {1, 2, 4, 8, 16, 32, 64, 128,
                                  1, 2, 4, 8, 16, 32, 64, 128};

    dim3 gFG(NTOT / 128, 2);
    dim3 gRS(NTOT / 128, 1);
    dim3 gH (NTOT / 128, 2);

    for (int i = 0; i < NBLK; i++) {
        int d = dil[i];
        if (d == 1)
            gemm_kernel<240, 0, 0, 256, 1><<<gFG, 256>>>(i, d, nullptr, nullptr);
        else if (d == 2)
            gemm_kernel<240, 0, 0, 256, 2><<<gFG, 256>>>(i, d, nullptr, nullptr);
        else
            gemm_kernel<240, 0, 0, 256, 4><<<gFG, 256>>>(i, d, nullptr, nullptr);
        gemm_kernel<128, 1, 1, 128, 4><<<gRS, 256>>>(i, 0, nullptr, nullptr);
    }
    gemm_kernel<2048, 1, 2, 256, 4><<<gH, 256>>>(0, 0, nullptr, nullptr);  // big skip GEMM
    gemm_kernel<256, 1, 3, 256, 4><<<gH, 256>>>(0, 0, b1, nullptr);        // head1
    gemm_kernel<256, 1, 4, 256, 4><<<gH, 256>>>(0, 0, b2, out);            // head2 -> logits
}

// round 7
// speedup vs baseline: 2.0258x; 2.0258x over previous
#include <cuda_runtime.h>
#include <cuda_bf16.h>
#include <cstdint>
#include <cstddef>

#define T_LEN 16384
#define NTOT  131072
#define NBLK  16

// ---------------- activation planes (bf16 hi/lo), time-major [n][ch] ----------------
__device__ __align__(16) __nv_bfloat16 g_Xh[(size_t)NTOT * 128];
__device__ __align__(16) __nv_bfloat16 g_Xl[(size_t)NTOT * 128];
__device__ __align__(16) __nv_bfloat16 g_Zh[(size_t)NBLK * NTOT * 128];
__device__ __align__(16) __nv_bfloat16 g_Zl[(size_t)NBLK * NTOT * 128];
__device__ __align__(16) __nv_bfloat16 g_Sh[(size_t)NTOT * 256];
__device__ __align__(16) __nv_bfloat16 g_Sl[(size_t)NTOT * 256];
__device__ __align__(16) __nv_bfloat16 g_Hh[(size_t)NTOT * 256];
__device__ __align__(16) __nv_bfloat16 g_Hl[(size_t)NTOT * 256];

// weight blocks per [ntile][kchunk]: [plane2][row128][k16] bf16 = 4096 elems = 8KB
__device__ __align__(16) __nv_bfloat16 g_WFG[(size_t)NBLK * 2 * 16 * 4096];
__device__ __align__(16) __nv_bfloat16 g_WRS[(size_t)NBLK * 8 * 4096];
__device__ __align__(16) __nv_bfloat16 g_WSK[(size_t)2 * 128 * 4096];
__device__ __align__(16) __nv_bfloat16 g_W1b[(size_t)2 * 16 * 4096];
__device__ __align__(16) __nv_bfloat16 g_W2b[(size_t)2 * 16 * 4096];
__device__ float g_Bsk[256];

// ---------------- helpers ----------------
__device__ __forceinline__ uint32_t smem_u32(const void* p) {
    uint32_t a;
    asm("{ .reg .u64 t; cvta.to.shared.u64 t, %1; cvt.u32.u64 %0, t; }" : "=r"(a) : "l"(p));
    return a;
}
__device__ __forceinline__ void bsplit(float v, __nv_bfloat16& h, __nv_bfloat16& l) {
    h = __float2bfloat16(v);
    l = __float2bfloat16(v - __bfloat162float(h));
}
__device__ __forceinline__ void store2(__nv_bfloat16* Ph, __nv_bfloat16* Pl, size_t off,
                                       float v0, float v1) {
    __nv_bfloat16 h0, l0, h1, l1;
    bsplit(v0, h0, l0); bsplit(v1, h1, l1);
    __nv_bfloat162 hp; hp.x = h0; hp.y = h1;
    __nv_bfloat162 lp; lp.x = l0; lp.y = l1;
    *reinterpret_cast<__nv_bfloat162*>(Ph + off) = hp;
    *reinterpret_cast<__nv_bfloat162*>(Pl + off) = lp;
}
__device__ __forceinline__ float safe_tanh(float x) {
    float ax = fabsf(x);
    float e = __expf(-2.0f * ax);
    return copysignf((1.0f - e) / (1.0f + e), x);
}
__device__ __forceinline__ float sigmoidf_(float x) { return 1.0f / (1.0f + __expf(-x)); }

// ---------------- packing ----------------
__global__ void pack_fg(const float* __restrict__ Wf, const float* __restrict__ Wg) {
    int idx = blockIdx.x * blockDim.x + threadIdx.x;   // 16*2*16*2048
    int kin = idx & 15, row = (idx >> 4) & 127, c = (idx >> 11) & 15;
    int nt = (idx >> 15) & 1, l = idx >> 16;
    int m = nt * 128 + row, ch = m >> 1, isg = m & 1;
    int tap = (c < 8) ? 1 : 0;
    int cin = (c & 7) * 16 + kin;
    float v = 0.f;
    if (ch < 120 && cin < 120) {
        const float* s = isg ? Wg : Wf;
        v = s[(((size_t)l * 120 + ch) * 120 + cin) * 2 + tap];
    }
    __nv_bfloat16 h, lo; bsplit(v, h, lo);
    __nv_bfloat16* blk = g_WFG + ((size_t)((l * 2 + nt) * 16 + c)) * 4096;
    blk[row * 16 + kin] = h;
    blk[2048 + row * 16 + kin] = lo;
}

__global__ void pack_rs(const float* __restrict__ Wres) {
    int idx = blockIdx.x * blockDim.x + threadIdx.x;   // 16*8*2048
    int kin = idx & 15, row = (idx >> 4) & 127, c = (idx >> 11) & 7, l = idx >> 14;
    int cin = c * 16 + kin;
    float v = (row < 120 && cin < 120) ? Wres[((size_t)l * 120 + row) * 120 + cin] : 0.f;
    __nv_bfloat16 h, lo; bsplit(v, h, lo);
    __nv_bfloat16* blk = g_WRS + ((size_t)(l * 8 + c)) * 4096;
    blk[row * 16 + kin] = h;
    blk[2048 + row * 16 + kin] = lo;
}

__global__ void pack_sk(const float* __restrict__ Wskip, const float* __restrict__ bskip) {
    int idx = blockIdx.x * blockDim.x + threadIdx.x;   // 2*128*2048
    int kin = idx & 15, row = (idx >> 4) & 127, c = (idx >> 11) & 127, nt = idx >> 18;
    int q = nt * 128 + row, lay = c >> 3, cin = (c & 7) * 16 + kin;
    float v = (q < 240 && cin < 120) ? Wskip[((size_t)lay * 240 + q) * 120 + cin] : 0.f;
    __nv_bfloat16 h, lo; bsplit(v, h, lo);
    __nv_bfloat16* blk = g_WSK + ((size_t)(nt * 128 + c)) * 4096;
    blk[row * 16 + kin] = h;
    blk[2048 + row * 16 + kin] = lo;
    if (idx < 256) {
        float s = 0.f;
        if (idx < 240) for (int j = 0; j < NBLK; j++) s += bskip[j * 240 + idx];
        g_Bsk[idx] = s;
    }
}

__global__ void pack_h(const float* __restrict__ W1, const float* __restrict__ W2) {
    int idx = blockIdx.x * blockDim.x + threadIdx.x;   // 2*16*2048
    int kin = idx & 15, row = (idx >> 4) & 127, c = (idx >> 11) & 15, nt = idx >> 15;
    int q = nt * 128 + row, k = c * 16 + kin;
    float v1 = (k < 240) ? W1[(size_t)q * 240 + k] : 0.f;
    float v2 = W2[(size_t)q * 256 + k];
    __nv_bfloat16 h, lo;
    __nv_bfloat16* b1 = g_W1b + ((size_t)(nt * 16 + c)) * 4096;
    __nv_bfloat16* b2 = g_W2b + ((size_t)(nt * 16 + c)) * 4096;
    bsplit(v1, h, lo); b1[row * 16 + kin] = h; b1[2048 + row * 16 + kin] = lo;
    bsplit(v2, h, lo); b2[row * 16 + kin] = h; b2[2048 + row * 16 + kin] = lo;
}

__global__ void init_kernel(const float* __restrict__ wave,
                            const float* __restrict__ W_in,
                            const float* __restrict__ b_in) {
    int idx = blockIdx.x * blockDim.x + threadIdx.x;   // NTOT*128
    int n = idx >> 7, c = idx & 127;
    float x = (c < 120) ? (W_in[c] * wave[n] + b_in[c]) : 0.f;
    __nv_bfloat16 h, l; bsplit(x, h, l);
    g_Xh[idx] = h; g_Xl[idx] = l;
}

// ---------------- asm macros ----------------
#define CPA16(dst, src, sz) \
    asm volatile("cp.async.cg.shared.global [%0], [%1], 16, %2;" \
                 :: "r"(dst), "l"(src), "r"(sz) : "memory")
#define CP_COMMIT() asm volatile("cp.async.commit_group;" ::: "memory")
#define CP_WAIT1()  asm volatile("cp.async.wait_group 1;" ::: "memory")

#define LDM4(rr, addr) \
    asm volatile("ldmatrix.sync.aligned.m8n8.x4.shared.b16 {%0,%1,%2,%3}, [%4];" \
                 : "=r"((rr)[0]), "=r"((rr)[1]), "=r"((rr)[2]), "=r"((rr)[3]) : "r"(addr))

#define MMA(cr, a, b0v, b1v) \
    asm volatile("mma.sync.aligned.m16n8k16.row.col.f32.bf16.bf16.f32 " \
                 "{%0,%1,%2,%3}, {%4,%5,%6,%7}, {%8,%9}, {%0,%1,%2,%3};" \
                 : "+f"((cr)[0]), "+f"((cr)[1]), "+f"((cr)[2]), "+f"((cr)[3]) \
                 : "r"((a)[0]), "r"((a)[1]), "r"((a)[2]), "r"((a)[3]), "r"(b0v), "r"(b1v))

// ---------------- main GEMM ----------------
// C[n][col] = sum_k A[n][k] * W[col][k], A = activations (hi+lo), W = weights (hi+lo)
// MODE 0 FG (N=256 f/g interleaved -> z), 1 RES (+=X), 2 SKIP (relu->S),
// MODE 3 H1 (relu->H), 4 H2 (logits->dout)
template<int MODE, int NCH>
__global__ void __launch_bounds__(256) mma_kernel(int layer, int dil,
                                                  const float* __restrict__ bA,
                                                  const float* __restrict__ bB,
                                                  float* __restrict__ dout) {
    // [buf][plane: Ah, Al, Wh, Wl][128 rows * 24 pitch]
    __shared__ __align__(16) __nv_bfloat16 sm[2][4][3072];

    const int tid = threadIdx.x;
    const int lane = tid & 31, wid = tid >> 5;
    const int wn = wid >> 2, wc = wid & 3;      // warp: 64 time x 32 ch
    const int n0 = blockIdx.x * 128;
    const int nt = blockIdx.y;

    const __nv_bfloat16 *Wfam, *APh, *APl;
    int wblk0, CHW;
    if (MODE == 0)      { Wfam = g_WFG; wblk0 = (layer * 2 + nt) * 16; APh = g_Xh; APl = g_Xl; CHW = 128; }
    else if (MODE == 1) { Wfam = g_WRS; wblk0 = layer * 8;
                          APh = g_Zh + (size_t)layer * NTOT * 128;
                          APl = g_Zl + (size_t)layer * NTOT * 128; CHW = 128; }
    else if (MODE == 2) { Wfam = g_WSK; wblk0 = nt * 128; APh = g_Zh; APl = g_Zl; CHW = 128; }
    else if (MODE == 3) { Wfam = g_W1b; wblk0 = nt * 16; APh = g_Sh; APl = g_Sl; CHW = 256; }
    else                { Wfam = g_W2b; wblk0 = nt * 16; APh = g_Hh; APl = g_Hl; CHW = 256; }

    const uint32_t smb = smem_u32(&sm[0][0][0]);

    // ldmatrix lane offsets (pitch 48B rows -> conflict-free)
    uint32_t offA[4], offB[2];
    {
        int rA = wn * 64 + (lane & 15);
        int cA = (lane >> 4) * 16;
#pragma unroll
        for (int i = 0; i < 4; i++) offA[i] = (uint32_t)((rA + i * 16) * 48 + cA);
        int rB = wc * 32 + (lane >> 4) * 8 + (lane & 7);
        int cB = ((lane >> 3) & 1) * 16;
        offB[0] = (uint32_t)(rB * 48 + cB);
        offB[1] = (uint32_t)((rB + 16) * 48 + cB);
    }

    float acc[4][4][4];
#pragma unroll
    for (int i = 0; i < 4; i++)
#pragma unroll
        for (int j = 0; j < 4; j++)
#pragma unroll
            for (int k = 0; k < 4; k++) acc[i][j][k] = 0.f;

#define STAGE(cc, s) do {                                                            \
        const __nv_bfloat16* wb_ = Wfam + (size_t)(wblk0 + (cc)) * 4096;             \
        _Pragma("unroll")                                                            \
        for (int ii = 0; ii < 2; ii++) {                                             \
            int u = tid + ii * 256, p = u >> 8, r = (u >> 1) & 127, hh = u & 1;      \
            uint32_t d = smb + (s) * 24576u + (2 + p) * 6144u + r * 48u + hh * 16u;  \
            CPA16(d, wb_ + p * 2048 + r * 16 + hh * 8, 16);                          \
        }                                                                            \
        int ch0_, sh_;                                                               \
        if (MODE == 0) { ch0_ = ((cc) & 7) * 16; sh_ = ((cc) < 8) ? 0 : dil; }       \
        else if (MODE == 2) { ch0_ = ((cc) & 7) * 16; sh_ = 0; }                     \
        else { ch0_ = (cc) * 16; sh_ = 0; }                                          \
        const __nv_bfloat16* ah_ = APh; const __nv_bfloat16* al_ = APl;              \
        if (MODE == 2) { size_t zo_ = (size_t)((cc) >> 3) * NTOT * 128;              \
                         ah_ += zo_; al_ += zo_; }                                   \
        _Pragma("unroll")                                                            \
        for (int ii = 0; ii < 2; ii++) {                                             \
            int u = tid + ii * 256, p = u >> 8, r = (u >> 1) & 127, hh = u & 1;      \
            int na = n0 + r; int sz = 16; int nn = na - sh_;                         \
            if (MODE == 0 && (cc) >= 8) {                                            \
                int t = na & (T_LEN - 1);                                            \
                if (t < sh_) { sz = 0; nn = na; }                                    \
            }                                                                        \
            uint32_t d = smb + (s) * 24576u + p * 6144u + r * 48u + hh * 16u;        \
            const __nv_bfloat16* gp = (p ? al_ : ah_) + (size_t)nn * CHW + ch0_ + hh * 8; \
            CPA16(d, gp, sz);                                                        \
        }                                                                            \
    } while (0)

    STAGE(0, 0);
    CP_COMMIT();

#pragma unroll 1
    for (int c = 0; c < NCH; c++) {
        if (c + 1 < NCH) STAGE(c + 1, (c + 1) & 1);
        CP_COMMIT();
        CP_WAIT1();
        __syncthreads();

        const uint32_t base = smb + (uint32_t)(c & 1) * 24576u;
        uint32_t Ah[4][4], Al[4][4], Bf[2][4];
#pragma unroll
        for (int i = 0; i < 4; i++) {
            LDM4(Ah[i], base + offA[i]);
            LDM4(Al[i], base + 6144u + offA[i]);
        }
        // W hi plane
        LDM4(Bf[0], base + 12288u + offB[0]);
        LDM4(Bf[1], base + 12288u + offB[1]);
#pragma unroll
        for (int i = 0; i < 4; i++)
#pragma unroll
            for (int j = 0; j < 4; j++)
                MMA(acc[i][j], Ah[i], Bf[j >> 1][(j & 1) * 2], Bf[j >> 1][(j & 1) * 2 + 1]);
#pragma unroll
        for (int i = 0; i < 4; i++)
#pragma unroll
            for (int j = 0; j < 4; j++)
                MMA(acc[i][j], Al[i], Bf[j >> 1][(j & 1) * 2], Bf[j >> 1][(j & 1) * 2 + 1]);
        // W lo plane
        LDM4(Bf[0], base + 18432u + offB[0]);
        LDM4(Bf[1], base + 18432u + offB[1]);
#pragma unroll
        for (int i = 0; i < 4; i++)
#pragma unroll
            for (int j = 0; j < 4; j++)
                MMA(acc[i][j], Ah[i], Bf[j >> 1][(j & 1) * 2], Bf[j >> 1][(j & 1) * 2 + 1]);

        __syncthreads();
    }
#undef STAGE

    // ---------------- epilogue ----------------
#pragma unroll
    for (int j = 0; j < 4; j++) {
        const int col = nt * 128 + wc * 32 + j * 8 + (lane & 3) * 2;
        float bv0 = 0.f, bv1 = 0.f;
        if (MODE == 0) {
            int cc = col >> 1;
            if (cc < 120) { bv0 = bA[layer * 120 + cc]; bv1 = bB[layer * 120 + cc]; }
        } else if (MODE == 1) {
            if (col < 120)     bv0 = bA[layer * 120 + col];
            if (col + 1 < 120) bv1 = bA[layer * 120 + col + 1];
        } else if (MODE == 2) {
            bv0 = g_Bsk[col]; bv1 = g_Bsk[col + 1];
        } else {
            bv0 = bA[col]; bv1 = bA[col + 1];
        }
#pragma unroll
        for (int i = 0; i < 4; i++)
#pragma unroll
            for (int h = 0; h < 2; h++) {
                int na = n0 + wn * 64 + i * 16 + h * 8 + (lane >> 2);
                float v0 = acc[i][j][h * 2], v1 = acc[i][j][h * 2 + 1];
                if (MODE == 0) {
                    int cc = col >> 1;
                    float z = safe_tanh(v0 + bv0) * sigmoidf_(v1 + bv1);
                    size_t off = (size_t)layer * NTOT * 128 + (size_t)na * 128 + cc;
                    __nv_bfloat16 zh, zl; bsplit(z, zh, zl);
                    g_Zh[off] = zh; g_Zl[off] = zl;
                } else if (MODE == 1) {
                    size_t off = (size_t)na * 128 + col;
                    __nv_bfloat162 xh = *reinterpret_cast<__nv_bfloat162*>(g_Xh + off);
                    __nv_bfloat162 xl = *reinterpret_cast<__nv_bfloat162*>(g_Xl + off);
                    float x0 = __bfloat162float(xh.x) + __bfloat162float(xl.x) + v0 + bv0;
                    float x1 = __bfloat162float(xh.y) + __bfloat162float(xl.y) + v1 + bv1;
                    store2(g_Xh, g_Xl, off, x0, x1);
                } else if (MODE == 2) {
                    store2(g_Sh, g_Sl, (size_t)na * 256 + col,
                           fmaxf(v0 + bv0, 0.f), fmaxf(v1 + bv1, 0.f));
                } else if (MODE == 3) {
                    store2(g_Hh, g_Hl, (size_t)na * 256 + col,
                           fmaxf(v0 + bv0, 0.f), fmaxf(v1 + bv1, 0.f));
                } else {
                    int b = na >> 14, t = na & (T_LEN - 1);
                    dout[((size_t)b * 256 + col) * T_LEN + t]     = v0 + bv0;
                    dout[((size_t)b * 256 + col + 1) * T_LEN + t] = v1 + bv1;
                }
            }
    }
}

// ---------------- launch ----------------
extern "C" void kernel_launch(void* const* d_in, const int* in_sizes, int n_in,
                              void* d_out, int out_size) {
    const float* wave  = (const float*)d_in[0];
    const float* W_in  = (const float*)d_in[1];
    const float* b_in  = (const float*)d_in[2];
    const float* Wf    = (const float*)d_in[3];
    const float* bf    = (const float*)d_in[4];
    const float* Wg    = (const float*)d_in[5];
    const float* bg    = (const float*)d_in[6];
    const float* Wres  = (const float*)d_in[7];
    const float* bres  = (const float*)d_in[8];
    const float* Wskip = (const float*)d_in[9];
    const float* bskip = (const float*)d_in[10];
    const float* W1    = (const float*)d_in[11];
    const float* b1    = (const float*)d_in[12];
    const float* W2    = (const float*)d_in[13];
    const float* b2    = (const float*)d_in[14];
    float* out = (float*)d_out;

    pack_fg<<<16 * 2 * 16 * 2048 / 256, 256>>>(Wf, Wg);
    pack_rs<<<16 * 8 * 2048 / 256, 256>>>(Wres);
    pack_sk<<<2 * 128 * 2048 / 256, 256>>>(Wskip, bskip);
    pack_h <<<2 * 16 * 2048 / 256, 256>>>(W1, W2);
    init_kernel<<<(size_t)NTOT * 128 / 256, 256>>>(wave, W_in, b_in);

    static const int dil[NBLK] = {1, 2, 4, 8, 16, 32, 64, 128,
                                  1, 2, 4, 8, 16, 32, 64, 128};

    dim3 g2(NTOT / 128, 2), g1(NTOT / 128, 1);

    for (int i = 0; i < NBLK; i++) {
        mma_kernel<0, 16><<<g2, 256>>>(i, dil[i], bf, bg, nullptr);
        mma_kernel<1, 8><<<g1, 256>>>(i, 0, bres, nullptr, nullptr);
    }
    mma_kernel<2, 128><<<g2, 256>>>(0, 0, nullptr, nullptr, nullptr);  // batched skip
    mma_kernel<3, 16><<<g2, 256>>>(0, 0, b1, nullptr, nullptr);        // head1
    mma_kernel<4, 16><<<g2, 256>>>(0, 0, b2, nullptr, out);            // head2
}

// round 8
// speedup vs baseline: 2.0370x; 1.0055x over previous
#include <cuda_runtime.h>
#include <cuda_bf16.h>
#include <cstdint>
#include <cstddef>

#define T_LEN 16384
#define NTOT  131072
#define NBLK  16

// ---------------- activation planes (bf16 hi/lo), time-major [n][ch] ----------------
__device__ __align__(16) __nv_bfloat16 g_Xh[2][(size_t)NTOT * 128];  // ping-pong residual
__device__ __align__(16) __nv_bfloat16 g_Xl[2][(size_t)NTOT * 128];
__device__ __align__(16) __nv_bfloat16 g_Zh[(size_t)NBLK * NTOT * 128];
__device__ __align__(16) __nv_bfloat16 g_Zl[(size_t)NBLK * NTOT * 128];
__device__ __align__(16) __nv_bfloat16 g_Sh[(size_t)NTOT * 256];
__device__ __align__(16) __nv_bfloat16 g_Sl[(size_t)NTOT * 256];
__device__ __align__(16) __nv_bfloat16 g_Hh[(size_t)NTOT * 256];
__device__ __align__(16) __nv_bfloat16 g_Hl[(size_t)NTOT * 256];

// weight blocks per [ntile][kchunk]: [plane2][row128][k16] bf16 = 4096 elems
__device__ __align__(16) __nv_bfloat16 g_WFG[(size_t)NBLK * 2 * 16 * 4096];
__device__ __align__(16) __nv_bfloat16 g_WRS[(size_t)NBLK * 8 * 4096];
__device__ __align__(16) __nv_bfloat16 g_WSK[(size_t)2 * 128 * 4096];
__device__ __align__(16) __nv_bfloat16 g_W1b[(size_t)2 * 16 * 4096];
__device__ __align__(16) __nv_bfloat16 g_W2b[(size_t)2 * 16 * 4096];
__device__ float g_Bsk[256];

// ---------------- helpers ----------------
__device__ __forceinline__ uint32_t smem_u32(const void* p) {
    uint32_t a;
    asm("{ .reg .u64 t; cvta.to.shared.u64 t, %1; cvt.u32.u64 %0, t; }" : "=r"(a) : "l"(p));
    return a;
}
__device__ __forceinline__ void bsplit(float v, __nv_bfloat16& h, __nv_bfloat16& l) {
    h = __float2bfloat16(v);
    l = __float2bfloat16(v - __bfloat162float(h));
}
__device__ __forceinline__ void store2(__nv_bfloat16* Ph, __nv_bfloat16* Pl, size_t off,
                                       float v0, float v1) {
    __nv_bfloat16 h0, l0, h1, l1;
    bsplit(v0, h0, l0); bsplit(v1, h1, l1);
    __nv_bfloat162 hp; hp.x = h0; hp.y = h1;
    __nv_bfloat162 lp; lp.x = l0; lp.y = l1;
    *reinterpret_cast<__nv_bfloat162*>(Ph + off) = hp;
    *reinterpret_cast<__nv_bfloat162*>(Pl + off) = lp;
}
__device__ __forceinline__ float safe_tanh(float x) {
    float ax = fabsf(x);
    float e = __expf(-2.0f * ax);
    return copysignf((1.0f - e) / (1.0f + e), x);
}
__device__ __forceinline__ float sigmoidf_(float x) { return 1.0f / (1.0f + __expf(-x)); }

// ---------------- packing ----------------
__global__ void pack_fg(const float* __restrict__ Wf, const float* __restrict__ Wg) {
    int idx = blockIdx.x * blockDim.x + threadIdx.x;
    int kin = idx & 15, row = (idx >> 4) & 127, c = (idx >> 11) & 15;
    int nt = (idx >> 15) & 1, l = idx >> 16;
    int m = nt * 128 + row, ch = m >> 1, isg = m & 1;
    int tap = (c < 8) ? 1 : 0;
    int cin = (c & 7) * 16 + kin;
    float v = 0.f;
    if (ch < 120 && cin < 120) {
        const float* s = isg ? Wg : Wf;
        v = s[(((size_t)l * 120 + ch) * 120 + cin) * 2 + tap];
    }
    __nv_bfloat16 h, lo; bsplit(v, h, lo);
    __nv_bfloat16* blk = g_WFG + ((size_t)((l * 2 + nt) * 16 + c)) * 4096;
    blk[row * 16 + kin] = h;
    blk[2048 + row * 16 + kin] = lo;
}

__global__ void pack_rs(const float* __restrict__ Wres) {
    int idx = blockIdx.x * blockDim.x + threadIdx.x;
    int kin = idx & 15, row = (idx >> 4) & 127, c = (idx >> 11) & 7, l = idx >> 14;
    int cin = c * 16 + kin;
    float v = (row < 120 && cin < 120) ? Wres[((size_t)l * 120 + row) * 120 + cin] : 0.f;
    __nv_bfloat16 h, lo; bsplit(v, h, lo);
    __nv_bfloat16* blk = g_WRS + ((size_t)(l * 8 + c)) * 4096;
    blk[row * 16 + kin] = h;
    blk[2048 + row * 16 + kin] = lo;
}

__global__ void pack_sk(const float* __restrict__ Wskip, const float* __restrict__ bskip) {
    int idx = blockIdx.x * blockDim.x + threadIdx.x;
    int kin = idx & 15, row = (idx >> 4) & 127, c = (idx >> 11) & 127, nt = idx >> 18;
    int q = nt * 128 + row, lay = c >> 3, cin = (c & 7) * 16 + kin;
    float v = (q < 240 && cin < 120) ? Wskip[((size_t)lay * 240 + q) * 120 + cin] : 0.f;
    __nv_bfloat16 h, lo; bsplit(v, h, lo);
    __nv_bfloat16* blk = g_WSK + ((size_t)(nt * 128 + c)) * 4096;
    blk[row * 16 + kin] = h;
    blk[2048 + row * 16 + kin] = lo;
    if (idx < 256) {
        float s = 0.f;
        if (idx < 240) for (int j = 0; j < NBLK; j++) s += bskip[j * 240 + idx];
        g_Bsk[idx] = s;
    }
}

__global__ void pack_h(const float* __restrict__ W1, const float* __restrict__ W2) {
    int idx = blockIdx.x * blockDim.x + threadIdx.x;
    int kin = idx & 15, row = (idx >> 4) & 127, c = (idx >> 11) & 15, nt = idx >> 15;
    int q = nt * 128 + row, k = c * 16 + kin;
    float v1 = (k < 240) ? W1[(size_t)q * 240 + k] : 0.f;
    float v2 = W2[(size_t)q * 256 + k];
    __nv_bfloat16 h, lo;
    __nv_bfloat16* b1 = g_W1b + ((size_t)(nt * 16 + c)) * 4096;
    __nv_bfloat16* b2 = g_W2b + ((size_t)(nt * 16 + c)) * 4096;
    bsplit(v1, h, lo); b1[row * 16 + kin] = h; b1[2048 + row * 16 + kin] = lo;
    bsplit(v2, h, lo); b2[row * 16 + kin] = h; b2[2048 + row * 16 + kin] = lo;
}

__global__ void init_kernel(const float* __restrict__ wave,
                            const float* __restrict__ W_in,
                            const float* __restrict__ b_in) {
    int idx = blockIdx.x * blockDim.x + threadIdx.x;
    int n = idx >> 7, c = idx & 127;
    float x = (c < 120) ? (W_in[c] * wave[n] + b_in[c]) : 0.f;
    __nv_bfloat16 h, l; bsplit(x, h, l);
    g_Xh[0][idx] = h; g_Xl[0][idx] = l;
}

// ---------------- asm macros ----------------
#define CPA16(dst, src, sz) \
    asm volatile("cp.async.cg.shared.global [%0], [%1], 16, %2;" \
                 :: "r"(dst), "l"(src), "r"(sz) : "memory")
#define CP_COMMIT() asm volatile("cp.async.commit_group;" ::: "memory")
#define CP_WAIT1()  asm volatile("cp.async.wait_group 1;" ::: "memory")

#define LDM4(rr, addr) \
    asm volatile("ldmatrix.sync.aligned.m8n8.x4.shared.b16 {%0,%1,%2,%3}, [%4];" \
                 : "=r"((rr)[0]), "=r"((rr)[1]), "=r"((rr)[2]), "=r"((rr)[3]) : "r"(addr))

#define MMA(cr, a, b0v, b1v) \
    asm volatile("mma.sync.aligned.m16n8k16.row.col.f32.bf16.bf16.f32 " \
                 "{%0,%1,%2,%3}, {%4,%5,%6,%7}, {%8,%9}, {%0,%1,%2,%3};" \
                 : "+f"((cr)[0]), "+f"((cr)[1]), "+f"((cr)[2]), "+f"((cr)[3]) \
                 : "r"((a)[0]), "r"((a)[1]), "r"((a)[2]), "r"((a)[3]), "r"(b0v), "r"(b1v))

// ---------------- fused FG + RES kernel ----------------
// CTA: 64 time x 256 fg-cols. SMEM: 2 stage bufs (30720B each) + z tile (2x17408B).
// Stage buf layout: Ah@0(3072) Al@3072 Wh@6144(12288) Wl@18432.
#define SLOTB 30720u
#define ZOFF  61440u
#define ZPITCH 272u
#define ZPL   17408u

__global__ void __launch_bounds__(256, 2) fgres_kernel(int layer, int dil,
        const float* __restrict__ bf, const float* __restrict__ bg,
        const float* __restrict__ bres) {
    extern __shared__ __align__(16) char sm[];
    const int tid = threadIdx.x, lane = tid & 31, wid = tid >> 5;
    const int wn = wid >> 2, wc = wid & 3;     // 2 time-groups x 4 col-groups
    const int n0 = blockIdx.x * 64;
    const uint32_t smb = smem_u32(sm);

    const __nv_bfloat16* Xrh = g_Xh[layer & 1];
    const __nv_bfloat16* Xrl = g_Xl[layer & 1];
    __nv_bfloat16* Xwh = g_Xh[(layer + 1) & 1];
    __nv_bfloat16* Xwl = g_Xl[(layer + 1) & 1];
    const __nv_bfloat16* Wb  = g_WFG + (size_t)layer * 2 * 16 * 4096;
    const __nv_bfloat16* WRb = g_WRS + (size_t)layer * 8 * 4096;

    uint32_t offA[2], offB[4], offRB[2], offZ;
    {
        int rA = wn * 32 + (lane & 15);
        offA[0] = (uint32_t)(rA * 48 + (lane >> 4) * 16);
        offA[1] = offA[0] + 16 * 48;
#pragma unroll
        for (int q = 0; q < 4; q++) {
            int rB = wc * 64 + q * 16 + (lane >> 4) * 8 + (lane & 7);
            offB[q] = (uint32_t)(rB * 48 + ((lane >> 3) & 1) * 16);
        }
#pragma unroll
        for (int q = 0; q < 2; q++) {
            int rB = wc * 32 + q * 16 + (lane >> 4) * 8 + (lane & 7);
            offRB[q] = (uint32_t)(rB * 48 + ((lane >> 3) & 1) * 16);
        }
        offZ = ZOFF + (uint32_t)((wn * 32 + (lane & 15)) * ZPITCH + (lane >> 4) * 16);
    }

    float acc[2][8][4];
#pragma unroll
    for (int i = 0; i < 2; i++)
#pragma unroll
        for (int j = 0; j < 8; j++)
#pragma unroll
            for (int k = 0; k < 4; k++) acc[i][j][k] = 0.f;

#define FSTAGE(cc, s) do {                                                       \
        _Pragma("unroll")                                                        \
        for (int ii = 0; ii < 4; ii++) {                                         \
            int u = tid + ii * 256, p = u >> 9, r = (u >> 1) & 255, hh = u & 1;  \
            uint32_t d = smb + (s) * SLOTB + 6144u + p * 12288u + r * 48u + hh * 16u; \
            const __nv_bfloat16* sp = Wb + ((size_t)((r >> 7) * 16 + (cc))) * 4096   \
                                      + p * 2048 + (r & 127) * 16 + hh * 8;      \
            CPA16(d, sp, 16);                                                    \
        }                                                                        \
        {                                                                        \
            int u = tid, p = u >> 7, r = (u >> 1) & 63, hh = u & 1;              \
            int na = n0 + r, nn = na, sz = 16, ch0;                              \
            if ((cc) < 8) ch0 = (cc) * 16;                                       \
            else {                                                               \
                ch0 = ((cc) - 8) * 16;                                           \
                int t = na & (T_LEN - 1);                                        \
                if (t >= dil) nn = na - dil; else sz = 0;                        \
            }                                                                    \
            uint32_t d = smb + (s) * SLOTB + p * 3072u + r * 48u + hh * 16u;     \
            const __nv_bfloat16* gp = (p ? Xrl : Xrh) + (size_t)nn * 128 + ch0 + hh * 8; \
            CPA16(d, gp, sz);                                                    \
        }                                                                        \
    } while (0)

    FSTAGE(0, 0);
    CP_COMMIT();
#pragma unroll 1
    for (int c = 0; c < 16; c++) {
        if (c + 1 < 16) FSTAGE(c + 1, (c + 1) & 1);
        CP_COMMIT();
        CP_WAIT1();
        __syncthreads();
        const uint32_t base = smb + (uint32_t)(c & 1) * SLOTB;
        uint32_t Ah[2][4], Al[2][4], Bf[4][4];
        LDM4(Ah[0], base + offA[0]); LDM4(Ah[1], base + offA[1]);
        LDM4(Al[0], base + 3072u + offA[0]); LDM4(Al[1], base + 3072u + offA[1]);
#pragma unroll
        for (int q = 0; q < 4; q++) LDM4(Bf[q], base + 6144u + offB[q]);
#pragma unroll
        for (int i = 0; i < 2; i++)
#pragma unroll
            for (int j = 0; j < 8; j++)
                MMA(acc[i][j], Ah[i], Bf[j >> 1][(j & 1) * 2], Bf[j >> 1][(j & 1) * 2 + 1]);
#pragma unroll
        for (int i = 0; i < 2; i++)
#pragma unroll
            for (int j = 0; j < 8; j++)
                MMA(acc[i][j], Al[i], Bf[j >> 1][(j & 1) * 2], Bf[j >> 1][(j & 1) * 2 + 1]);
#pragma unroll
        for (int q = 0; q < 4; q++) LDM4(Bf[q], base + 18432u + offB[q]);
#pragma unroll
        for (int i = 0; i < 2; i++)
#pragma unroll
            for (int j = 0; j < 8; j++)
                MMA(acc[i][j], Ah[i], Bf[j >> 1][(j & 1) * 2], Bf[j >> 1][(j & 1) * 2 + 1]);
        __syncthreads();
    }
#undef FSTAGE

    // ---- epilogue 1: z = tanh(f+bf)*sigmoid(g+bg) -> SMEM + gmem ----
#pragma unroll
    for (int j = 0; j < 8; j++) {
        int ch = wc * 32 + j * 4 + (lane & 3);
        float bfv = 0.f, bgv = 0.f;
        if (ch < 120) { bfv = bf[layer * 120 + ch]; bgv = bg[layer * 120 + ch]; }
#pragma unroll
        for (int i = 0; i < 2; i++)
#pragma unroll
            for (int h = 0; h < 2; h++) {
                int row = wn * 32 + i * 16 + h * 8 + (lane >> 2);
                float z = safe_tanh(acc[i][j][h * 2] + bfv) *
                          sigmoidf_(acc[i][j][h * 2 + 1] + bgv);
                __nv_bfloat16 zh, zl; bsplit(z, zh, zl);
                *reinterpret_cast<__nv_bfloat16*>(sm + ZOFF + row * ZPITCH + ch * 2) = zh;
                *reinterpret_cast<__nv_bfloat16*>(sm + ZOFF + ZPL + row * ZPITCH + ch * 2) = zl;
                size_t off = (size_t)layer * NTOT * 128 + (size_t)(n0 + row) * 128 + ch;
                g_Zh[off] = zh; g_Zl[off] = zl;
            }
    }

    // ---- res GEMM: racc[64t x 128ch] = z @ Wres^T ----
    float racc[2][4][4];
#pragma unroll
    for (int i = 0; i < 2; i++)
#pragma unroll
        for (int j = 0; j < 4; j++)
#pragma unroll
            for (int k = 0; k < 4; k++) racc[i][j][k] = 0.f;

#define RSTAGE(rc, s) do {                                                       \
        _Pragma("unroll")                                                        \
        for (int ii = 0; ii < 2; ii++) {                                         \
            int u = tid + ii * 256, p = u >> 8, r = (u >> 1) & 127, hh = u & 1;  \
            uint32_t d = smb + (s) * SLOTB + 6144u + p * 12288u + r * 48u + hh * 16u; \
            const __nv_bfloat16* sp = WRb + (size_t)(rc) * 4096 + p * 2048 + r * 16 + hh * 8; \
            CPA16(d, sp, 16);                                                    \
        }                                                                        \
    } while (0)

    RSTAGE(0, 0);
    CP_COMMIT();
#pragma unroll 1
    for (int rc = 0; rc < 8; rc++) {
        if (rc + 1 < 8) RSTAGE(rc + 1, (rc + 1) & 1);
        CP_COMMIT();
        CP_WAIT1();
        __syncthreads();
        const uint32_t base = smb + (uint32_t)(rc & 1) * SLOTB;
        uint32_t ZAh[2][4], ZAl[2][4], RB[2][4];
        uint32_t zo = offZ + rc * 32;
        LDM4(ZAh[0], smb + zo); LDM4(ZAh[1], smb + zo + 16 * ZPITCH);
        LDM4(ZAl[0], smb + ZPL + zo); LDM4(ZAl[1], smb + ZPL + zo + 16 * ZPITCH);
        LDM4(RB[0], base + 6144u + offRB[0]); LDM4(RB[1], base + 6144u + offRB[1]);
#pragma unroll
        for (int i = 0; i < 2; i++)
#pragma unroll
            for (int j = 0; j < 4; j++)
                MMA(racc[i][j], ZAh[i], RB[j >> 1][(j & 1) * 2], RB[j >> 1][(j & 1) * 2 + 1]);
#pragma unroll
        for (int i = 0; i < 2; i++)
#pragma unroll
            for (int j = 0; j < 4; j++)
                MMA(racc[i][j], ZAl[i], RB[j >> 1][(j & 1) * 2], RB[j >> 1][(j & 1) * 2 + 1]);
        LDM4(RB[0], base + 18432u + offRB[0]); LDM4(RB[1], base + 18432u + offRB[1]);
#pragma unroll
        for (int i = 0; i < 2; i++)
#pragma unroll
            for (int j = 0; j < 4; j++)
                MMA(racc[i][j], ZAh[i], RB[j >> 1][(j & 1) * 2], RB[j >> 1][(j & 1) * 2 + 1]);
        __syncthreads();
    }
#undef RSTAGE

    // ---- epilogue 2: X_next = X_cur + res + bres ----
#pragma unroll
    for (int j = 0; j < 4; j++) {
        int col = wc * 32 + j * 8 + (lane & 3) * 2;
        if (col < 120) {
            float bv0 = bres[layer * 120 + col];
            float bv1 = bres[layer * 120 + col + 1];
#pragma unroll
            for (int i = 0; i < 2; i++)
#pragma unroll
                for (int h = 0; h < 2; h++) {
                    int row = n0 + wn * 32 + i * 16 + h * 8 + (lane >> 2);
                    size_t off = (size_t)row * 128 + col;
                    __nv_bfloat162 xh = *reinterpret_cast<const __nv_bfloat162*>(Xrh + off);
                    __nv_bfloat162 xl = *reinterpret_cast<const __nv_bfloat162*>(Xrl + off);
                    float x0 = __bfloat162float(xh.x) + __bfloat162float(xl.x)
                             + racc[i][j][h * 2] + bv0;
                    float x1 = __bfloat162float(xh.y) + __bfloat162float(xl.y)
                             + racc[i][j][h * 2 + 1] + bv1;
                    store2(Xwh, Xwl, off, x0, x1);
                }
        }
    }
}

// ---------------- generic GEMM (SKIP / H1 / H2) — proven R7 path ----------------
template<int MODE, int NCH>
__global__ void __launch_bounds__(256) mma_kernel(const float* __restrict__ bA,
                                                  float* __restrict__ dout) {
    __shared__ __align__(16) __nv_bfloat16 smg[2][4][3072];

    const int tid = threadIdx.x;
    const int lane = tid & 31, wid = tid >> 5;
    const int wn = wid >> 2, wc = wid & 3;
    const int n0 = blockIdx.x * 128;
    const int nt = blockIdx.y;

    const __nv_bfloat16 *Wfam, *APh, *APl;
    int wblk0, CHW;
    if (MODE == 2)      { Wfam = g_WSK; wblk0 = nt * 128; APh = g_Zh; APl = g_Zl; CHW = 128; }
    else if (MODE == 3) { Wfam = g_W1b; wblk0 = nt * 16; APh = g_Sh; APl = g_Sl; CHW = 256; }
    else                { Wfam = g_W2b; wblk0 = nt * 16; APh = g_Hh; APl = g_Hl; CHW = 256; }

    const uint32_t smb = smem_u32(&smg[0][0][0]);

    uint32_t offA[4], offB[2];
    {
        int rA = wn * 64 + (lane & 15);
        int cA = (lane >> 4) * 16;
#pragma unroll
        for (int i = 0; i < 4; i++) offA[i] = (uint32_t)((rA + i * 16) * 48 + cA);
        int rB = wc * 32 + (lane >> 4) * 8 + (lane & 7);
        int cB = ((lane >> 3) & 1) * 16;
        offB[0] = (uint32_t)(rB * 48 + cB);
        offB[1] = (uint32_t)((rB + 16) * 48 + cB);
    }

    float acc[4][4][4];
#pragma unroll
    for (int i = 0; i < 4; i++)
#pragma unroll
        for (int j = 0; j < 4; j++)
#pragma unroll
            for (int k = 0; k < 4; k++) acc[i][j][k] = 0.f;

#define STAGE(cc, s) do {                                                            \
        const __nv_bfloat16* wb_ = Wfam + (size_t)(wblk0 + (cc)) * 4096;             \
        _Pragma("unroll")                                                            \
        for (int ii = 0; ii < 2; ii++) {                                             \
            int u = tid + ii * 256, p = u >> 8, r = (u >> 1) & 127, hh = u & 1;      \
            uint32_t d = smb + (s) * 24576u + (2 + p) * 6144u + r * 48u + hh * 16u;  \
            CPA16(d, wb_ + p * 2048 + r * 16 + hh * 8, 16);                          \
        }                                                                            \
        int ch0_;                                                                    \
        if (MODE == 2) ch0_ = ((cc) & 7) * 16; else ch0_ = (cc) * 16;                \
        const __nv_bfloat16* ah_ = APh; const __nv_bfloat16* al_ = APl;              \
        if (MODE == 2) { size_t zo_ = (size_t)((cc) >> 3) * NTOT * 128;              \
                         ah_ += zo_; al_ += zo_; }                                   \
        _Pragma("unroll")                                                            \
        for (int ii = 0; ii < 2; ii++) {                                             \
            int u = tid + ii * 256, p = u >> 8, r = (u >> 1) & 127, hh = u & 1;      \
            int na = n0 + r;                                                         \
            uint32_t d = smb + (s) * 24576u + p * 6144u + r * 48u + hh * 16u;        \
            const __nv_bfloat16* gp = (p ? al_ : ah_) + (size_t)na * CHW + ch0_ + hh * 8; \
            CPA16(d, gp, 16);                                                        \
        }                                                                            \
    } while (0)

    STAGE(0, 0);
    CP_COMMIT();
#pragma unroll 1
    for (int c = 0; c < NCH; c++) {
        if (c + 1 < NCH) STAGE(c + 1, (c + 1) & 1);
        CP_COMMIT();
        CP_WAIT1();
        __syncthreads();

        const uint32_t base = smb + (uint32_t)(c & 1) * 24576u;
        uint32_t Ah[4][4], Al[4][4], Bf[2][4];
#pragma unroll
        for (int i = 0; i < 4; i++) {
            LDM4(Ah[i], base + offA[i]);
            LDM4(Al[i], base + 6144u + offA[i]);
        }
        LDM4(Bf[0], base + 12288u + offB[0]);
        LDM4(Bf[1], base + 12288u + offB[1]);
#pragma unroll
        for (int i = 0; i < 4; i++)
#pragma unroll
            for (int j = 0; j < 4; j++)
                MMA(acc[i][j], Ah[i], Bf[j >> 1][(j & 1) * 2], Bf[j >> 1][(j & 1) * 2 + 1]);
#pragma unroll
        for (int i = 0; i < 4; i++)
#pragma unroll
            for (int j = 0; j < 4; j++)
                MMA(acc[i][j], Al[i], Bf[j >> 1][(j & 1) * 2], Bf[j >> 1][(j & 1) * 2 + 1]);
        LDM4(Bf[0], base + 18432u + offB[0]);
        LDM4(Bf[1], base + 18432u + offB[1]);
#pragma unroll
        for (int i = 0; i < 4; i++)
#pragma unroll
            for (int j = 0; j < 4; j++)
                MMA(acc[i][j], Ah[i], Bf[j >> 1][(j & 1) * 2], Bf[j >> 1][(j & 1) * 2 + 1]);
        __syncthreads();
    }
#undef STAGE

#pragma unroll
    for (int j = 0; j < 4; j++) {
        const int col = nt * 128 + wc * 32 + j * 8 + (lane & 3) * 2;
        float bv0, bv1;
        if (MODE == 2) { bv0 = g_Bsk[col]; bv1 = g_Bsk[col + 1]; }
        else           { bv0 = bA[col]; bv1 = bA[col + 1]; }
#pragma unroll
        for (int i = 0; i < 4; i++)
#pragma unroll
            for (int h = 0; h < 2; h++) {
                int na = n0 + wn * 64 + i * 16 + h * 8 + (lane >> 2);
                float v0 = acc[i][j][h * 2], v1 = acc[i][j][h * 2 + 1];
                if (MODE == 2) {
                    store2(g_Sh, g_Sl, (size_t)na * 256 + col,
                           fmaxf(v0 + bv0, 0.f), fmaxf(v1 + bv1, 0.f));
                } else if (MODE == 3) {
                    store2(g_Hh, g_Hl, (size_t)na * 256 + col,
                           fmaxf(v0 + bv0, 0.f), fmaxf(v1 + bv1, 0.f));
                } else {
                    int b = na >> 14, t = na & (T_LEN - 1);
                    dout[((size_t)b * 256 + col) * T_LEN + t]     = v0 + bv0;
                    dout[((size_t)b * 256 + col + 1) * T_LEN + t] = v1 + bv1;
                }
            }
    }
}

// ---------------- launch ----------------
extern "C" void kernel_launch(void* const* d_in, const int* in_sizes, int n_in,
                              void* d_out, int out_size) {
    const float* wave  = (const float*)d_in[0];
    const float* W_in  = (const float*)d_in[1];
    const float* b_in  = (const float*)d_in[2];
    const float* Wf    = (const float*)d_in[3];
    const float* bf    = (const float*)d_in[4];
    const float* Wg    = (const float*)d_in[5];
    const float* bg    = (const float*)d_in[6];
    const float* Wres  = (const float*)d_in[7];
    const float* bres  = (const float*)d_in[8];
    const float* Wskip = (const float*)d_in[9];
    const float* bskip = (const float*)d_in[10];
    const float* W1    = (const float*)d_in[11];
    const float* b1    = (const float*)d_in[12];
    const float* W2    = (const float*)d_in[13];
    const float* b2    = (const float*)d_in[14];
    float* out = (float*)d_out;

    const int FS = 96256;   // 2*30720 staging + 2*17408 z
    cudaFuncSetAttribute(fgres_kernel, cudaFuncAttributeMaxDynamicSharedMemorySize, FS);

    pack_fg<<<16 * 2 * 16 * 2048 / 256, 256>>>(Wf, Wg);
    pack_rs<<<16 * 8 * 2048 / 256, 256>>>(Wres);
    pack_sk<<<2 * 128 * 2048 / 256, 256>>>(Wskip, bskip);
    pack_h <<<2 * 16 * 2048 / 256, 256>>>(W1, W2);
    init_kernel<<<(size_t)NTOT * 128 / 256, 256>>>(wave, W_in, b_in);

    static const int dil[NBLK] = {1, 2, 4, 8, 16, 32, 64, 128,
                                  1, 2, 4, 8, 16, 32, 64, 128};

    for (int i = 0; i < NBLK; i++)
        fgres_kernel<<<NTOT / 64, 256, FS>>>(i, dil[i], bf, bg, bres);

    dim3 g2(NTOT / 128, 2);
    mma_kernel<2, 128><<<g2, 256>>>(nullptr, nullptr);  // batched skip
    mma_kernel<3, 16><<<g2, 256>>>(b1, nullptr);        // head1
    mma_kernel<4, 16><<<g2, 256>>>(b2, out);            // head2
}